// round 16
// baseline (speedup 1.0000x reference)
#include <cuda_runtime.h>
#include <cuda_bf16.h>

#define TT    65536
#define BB    4
#define W     16
#define NL    18
#define TILEC 256          // ts per CTA (4 warps x 64)
#define NTH   128
#define ZR    72           // zbuf row stride: >=64 (64 ts/warp row!) and mod 32 == 8
#define TFMASK 0xFFFFE000u

// smem float offsets
#define CONVA 0            // conv A frags: ((blk*6+c)*2+hl)*128, 3072 floats
#define RESA  3072         // res A frags: (rc*2+hl)*128, 512 floats
#define MIXO  3584
#define CBO   3600
#define GBO   3616
#define RBO   3632
#define TILEO 3648         // fp32 tile hT[ch][Rt]

typedef unsigned long long u64;
typedef unsigned int u32;

__device__ float g_h0[(size_t)BB * TT * W];   // [b][t][ch]
__device__ float g_h1[(size_t)BB * TT * W];

__device__ __forceinline__ u64 pk(float lo, float hi){ u64 r; asm("mov.b64 %0,{%1,%2};":"=l"(r):"f"(lo),"f"(hi)); return r; }
__device__ __forceinline__ u64 pk2(float x){ u64 r; asm("mov.b64 %0,{%1,%1};":"=l"(r):"f"(x)); return r; }
__device__ __forceinline__ void unpk(u64 v, float& lo, float& hi){ asm("mov.b64 {%0,%1},%2;":"=f"(lo),"=f"(hi):"l"(v)); }
__device__ __forceinline__ u64 fma2(u64 a, u64 b, u64 c){ u64 d; asm("fma.rn.f32x2 %0,%1,%2,%3;":"=l"(d):"l"(a),"l"(b),"l"(c)); return d; }
__device__ __forceinline__ u64 mul2(u64 a, u64 b){ u64 d; asm("mul.rn.f32x2 %0,%1,%2;":"=l"(d):"l"(a),"l"(b)); return d; }
__device__ __forceinline__ u64 add2(u64 a, u64 b){ u64 d; asm("add.rn.f32x2 %0,%1,%2;":"=l"(d):"l"(a),"l"(b)); return d; }
__device__ __forceinline__ float rcpf(float x){ float r; asm("rcp.approx.f32 %0,%1;":"=f"(r):"f"(x)); return r; }

#define ABS2 0x7FFFFFFF7FFFFFFFull
#define ONE2 0x3F8000003F800000ull

__device__ __forceinline__ u64 ssz(u64 f, u64 g){
    u64 df = add2(f & ABS2, ONE2);
    u64 dg = add2(g & ABS2, ONE2);
    u64 dd = mul2(df, dg);
    float dl, dh; unpk(dd, dl, dh);
    u64 rr = pk(rcpf(dl), rcpf(dh));
    return mul2(mul2(f, g), rr);
}

__device__ __forceinline__ void mma8(float* d, const u32* a, u32 b0, u32 b1){
    asm volatile(
        "mma.sync.aligned.m16n8k8.row.col.f32.tf32.tf32.f32 "
        "{%0,%1,%2,%3}, {%4,%5,%6,%7}, {%8,%9}, {%0,%1,%2,%3};"
        : "+f"(d[0]), "+f"(d[1]), "+f"(d[2]), "+f"(d[3])
        : "r"(a[0]), "r"(a[1]), "r"(a[2]), "r"(a[3]), "r"(b0), "r"(b1));
}

__device__ __forceinline__ void tfsplit(float x, u32& hi, u32& lo){
    u32 xb = __float_as_uint(x) & TFMASK;
    hi = xb;
    lo = __float_as_uint(x - __uint_as_float(xb));
}

__global__ void start_kernel(const float* __restrict__ x,
                             const float* __restrict__ sw,
                             float* __restrict__ out) {
    int idx = blockIdx.x * blockDim.x + threadIdx.x;
    if (idx < BB * TT) {
        float xv = x[idx];
        #pragma unroll
        for (int o = 0; o < W; o++) g_h0[(size_t)idx * W + o] = sw[o] * xv;
        out[idx] = 0.f;
    }
}

__host__ __device__ __forceinline__ int padRt(int d) {
    int R = TILEC + 2 * d;
    R += ((8 - (R & 31)) + 32) & 31;   // R % 32 == 8
    return R;
}

// A-fragment swizzle: value (o row 0..15, kk col 0..7) ->
//   lane = (o&7)*4 + (kk&3); reg = (o>>3) + 2*(kk>>2)
__device__ __forceinline__ int fragpos(int o, int kk){
    return ((o & 7) * 4 + (kk & 3)) * 4 + (o >> 3) + 2 * (kk >> 2);
}

__global__ __launch_bounds__(NTH, 4)
void layer15_kernel(const float* __restrict__ cw, const float* __restrict__ cb,
                    const float* __restrict__ gw, const float* __restrict__ gb,
                    const float* __restrict__ rw, const float* __restrict__ rb,
                    const float* __restrict__ mix, float* __restrict__ out,
                    int li, int d, int last)
{
    extern __shared__ float sh[];
    const float* hin  = (li & 1) ? g_h1 : g_h0;
    float*       hout = (li & 1) ? g_h0 : g_h1;
    const int b   = blockIdx.y;
    const int t0  = blockIdx.x * TILEC;
    const int tid = threadIdx.x;
    const int Rt  = padRt(d);
    float* hT = sh + TILEO;
    float* zb = hT + 16 * Rt;

    // ---- conv/gate A prep: tf32 hi/lo split, fragment-swizzled ----
    for (int idx = tid; idx < 1536; idx += NTH) {
        int blk = idx / 768, rem = idx - blk * 768;
        int o = rem / 48, ik = rem - o * 48;
        int i = ik / 3, kt = ik - i * 3;
        float wv = (blk ? gw : cw)[li * 768 + rem];
        u32 hb = __float_as_uint(wv) & TFMASK;
        float hi = __uint_as_float(hb);
        int c = kt * 2 + (i >> 3);
        int base = CONVA + ((blk * 6 + c) * 2) * 128 + fragpos(o, i & 7);
        sh[base]       = hi;
        sh[base + 128] = wv - hi;
    }
    // ---- res A prep ----
    for (int idx = tid; idx < 256; idx += NTH) {
        int o = idx >> 4, i = idx & 15;
        float v = last ? 0.f : rw[li * 256 + idx];
        u32 hb = __float_as_uint(v) & TFMASK;
        float hi = __uint_as_float(hb);
        int base = RESA + ((i >> 3) * 2) * 128 + fragpos(o, i & 7);
        sh[base]       = hi;
        sh[base + 128] = v - hi;
    }
    if (tid < 16) {
        sh[MIXO + tid] = mix[li * 16 + tid];
        sh[CBO  + tid] = cb[li * 16 + tid];
        sh[GBO  + tid] = gb[li * 16 + tid];
        sh[RBO  + tid] = last ? 0.f : rb[li * 16 + tid];
    }

    // ---- fp32 tile load (channel-major, conflict-free) ----
    {
        const int nrows = TILEC + 2 * d;
        for (int r = tid; r < nrows; r += NTH) {
            int gt = t0 - 2 * d + r;
            float4 v0, v1, v2, v3;
            if (gt >= 0) {
                const float4* s = (const float4*)(hin + ((size_t)b * TT + gt) * W);
                v0 = s[0]; v1 = s[1]; v2 = s[2]; v3 = s[3];
            } else {
                v0 = v1 = v2 = v3 = make_float4(0.f, 0.f, 0.f, 0.f);
            }
            hT[ 0 * Rt + r] = v0.x; hT[ 1 * Rt + r] = v0.y;
            hT[ 2 * Rt + r] = v0.z; hT[ 3 * Rt + r] = v0.w;
            hT[ 4 * Rt + r] = v1.x; hT[ 5 * Rt + r] = v1.y;
            hT[ 6 * Rt + r] = v1.z; hT[ 7 * Rt + r] = v1.w;
            hT[ 8 * Rt + r] = v2.x; hT[ 9 * Rt + r] = v2.y;
            hT[10 * Rt + r] = v2.z; hT[11 * Rt + r] = v2.w;
            hT[12 * Rt + r] = v3.x; hT[13 * Rt + r] = v3.y;
            hT[14 * Rt + r] = v3.z; hT[15 * Rt + r] = v3.w;
        }
    }
    __syncthreads();

    // ---- per-warp 64-ts tile ----
    const int lane = tid & 31;
    const int wid  = tid >> 5;
    const int gID  = lane >> 2;
    const int c4   = lane & 3;
    const int tloc = 2 * d + wid * 64;
    const int tw   = t0 + wid * 64;
    float* zw = zb + wid * (16 * ZR);

    // ---- conv+gate GEMM (3xTF32) ----
    float Df[8][4], Dg[8][4];
    {
        float cbl = sh[CBO + gID], cbh = sh[CBO + 8 + gID];
        float gbl = sh[GBO + gID], gbh = sh[GBO + 8 + gID];
        #pragma unroll
        for (int tsb = 0; tsb < 8; tsb++) {
            Df[tsb][0] = cbl; Df[tsb][1] = cbl; Df[tsb][2] = cbh; Df[tsb][3] = cbh;
            Dg[tsb][0] = gbl; Dg[tsb][1] = gbl; Dg[tsb][2] = gbh; Dg[tsb][3] = gbh;
        }
    }

    #pragma unroll
    for (int c = 0; c < 6; c++) {
        const int kt = c >> 1, iB = (c & 1) * 8;
        uint4 AFh = *(const uint4*)&sh[CONVA + ((0*6 + c) * 2 + 0) * 128 + lane * 4];
        uint4 AFl = *(const uint4*)&sh[CONVA + ((0*6 + c) * 2 + 1) * 128 + lane * 4];
        uint4 AGh = *(const uint4*)&sh[CONVA + ((1*6 + c) * 2 + 0) * 128 + lane * 4];
        uint4 AGl = *(const uint4*)&sh[CONVA + ((1*6 + c) * 2 + 1) * 128 + lane * 4];
        const float* t0p = hT + (iB + c4) * Rt;
        const float* t1p = hT + (iB + c4 + 4) * Rt;
        const int tb = tloc - (2 - kt) * d + gID;
        float b0v[8], b1v[8];
        #pragma unroll
        for (int tsb = 0; tsb < 8; tsb++) {
            b0v[tsb] = t0p[tb + tsb * 8];
            b1v[tsb] = t1p[tb + tsb * 8];
        }
        #pragma unroll
        for (int tsb = 0; tsb < 8; tsb++) {
            u32 b0h, b0l, b1h, b1l;
            tfsplit(b0v[tsb], b0h, b0l);
            tfsplit(b1v[tsb], b1h, b1l);
            mma8(Df[tsb], (const u32*)&AFh, b0h, b1h);
            mma8(Dg[tsb], (const u32*)&AGh, b0h, b1h);
            mma8(Df[tsb], (const u32*)&AFh, b0l, b1l);
            mma8(Dg[tsb], (const u32*)&AGh, b0l, b1l);
            mma8(Df[tsb], (const u32*)&AFl, b0h, b1h);
            mma8(Dg[tsb], (const u32*)&AGl, b0h, b1h);
        }
    }

    // ---- gated activation, z -> per-warp zbuf ----
    #pragma unroll
    for (int tsb = 0; tsb < 8; tsb++) {
        u64 z01 = ssz(pk(Df[tsb][0], Df[tsb][1]), pk(Dg[tsb][0], Dg[tsb][1]));
        u64 z23 = ssz(pk(Df[tsb][2], Df[tsb][3]), pk(Dg[tsb][2], Dg[tsb][3]));
        *(u64*)&zw[gID * ZR       + tsb * 8 + 2 * c4] = z01;
        *(u64*)&zw[(gID + 8) * ZR + tsb * 8 + 2 * c4] = z23;
    }
    __syncwarp();

    // ---- mixer: scalar fma2; lane owns ts pair 2*lane ----
    {
        const int t2 = 2 * lane;
        u64 acc = 0ull;
        #pragma unroll
        for (int p = 0; p < 16; p++) {
            u64 zz = *(const u64*)&zw[p * ZR + t2];
            acc = fma2(pk2(sh[MIXO + p]), zz, acc);
        }
        float a, c; unpk(acc, a, c);
        float2* op = (float2*)(out + (size_t)b * TT + tw + t2);
        float2 ov = *op;
        ov.x += a; ov.y += c;
        *op = ov;
    }

    // ---- residual GEMM + hout stores ----
    if (!last) {
        float Dr[8][4];
        {
            float rbl = sh[RBO + gID], rbh = sh[RBO + 8 + gID];
            #pragma unroll
            for (int tsb = 0; tsb < 8; tsb++) {
                int t = tloc + tsb * 8 + 2 * c4;
                float h0, h1, h2, h3;
                { u64 v = *(const u64*)&hT[gID * Rt + t];       unpk(v, h0, h1); }
                { u64 v = *(const u64*)&hT[(gID + 8) * Rt + t]; unpk(v, h2, h3); }
                Dr[tsb][0] = h0 + rbl; Dr[tsb][1] = h1 + rbl;
                Dr[tsb][2] = h2 + rbh; Dr[tsb][3] = h3 + rbh;
            }
        }
        #pragma unroll
        for (int rc = 0; rc < 2; rc++) {
            uint4 ARh = *(const uint4*)&sh[RESA + (rc * 2 + 0) * 128 + lane * 4];
            uint4 ARl = *(const uint4*)&sh[RESA + (rc * 2 + 1) * 128 + lane * 4];
            const float* z0p = zw + (rc * 8 + c4) * ZR + gID;
            const float* z1p = zw + (rc * 8 + c4 + 4) * ZR + gID;
            float b0v[8], b1v[8];
            #pragma unroll
            for (int tsb = 0; tsb < 8; tsb++) {
                b0v[tsb] = z0p[tsb * 8];
                b1v[tsb] = z1p[tsb * 8];
            }
            #pragma unroll
            for (int tsb = 0; tsb < 8; tsb++) {
                u32 b0h, b0l, b1h, b1l;
                tfsplit(b0v[tsb], b0h, b0l);
                tfsplit(b1v[tsb], b1h, b1l);
                mma8(Dr[tsb], (const u32*)&ARh, b0h, b1h);
                mma8(Dr[tsb], (const u32*)&ARh, b0l, b1l);
                mma8(Dr[tsb], (const u32*)&ARl, b0h, b1h);
            }
        }
        #pragma unroll
        for (int tsb = 0; tsb < 8; tsb++) {
            size_t base = ((size_t)b * TT + tw + tsb * 8 + 2 * c4) * W;
            hout[base + gID]         = Dr[tsb][0];
            hout[base + W + gID]     = Dr[tsb][1];
            hout[base + gID + 8]     = Dr[tsb][2];
            hout[base + W + gID + 8] = Dr[tsb][3];
        }
    }
}

extern "C" void kernel_launch(void* const* d_in, const int* in_sizes, int n_in,
                              void* d_out, int out_size) {
    const float* x   = (const float*)d_in[0];
    const float* sw  = (const float*)d_in[1];
    const float* cw  = (const float*)d_in[2];
    const float* cb  = (const float*)d_in[3];
    const float* gw  = (const float*)d_in[4];
    const float* gb  = (const float*)d_in[5];
    const float* rw  = (const float*)d_in[6];
    const float* rb  = (const float*)d_in[7];
    const float* mix = (const float*)d_in[8];
    float* out = (float*)d_out;

    static const int dil[NL] = {1,2,4,8,16,32,64,128,256,
                                1,2,4,8,16,32,64,128,256};

    const int max_smem = (TILEO + 16 * padRt(256) + 4 * 16 * ZR) * (int)sizeof(float);
    cudaFuncSetAttribute(layer15_kernel,
                         cudaFuncAttributeMaxDynamicSharedMemorySize, max_smem);

    start_kernel<<<(BB * TT + 255) / 256, 256>>>(x, sw, out);

    dim3 grid(TT / TILEC, BB);
    for (int li = 0; li < NL; li++) {
        int d = dil[li];
        int smem = (TILEO + 16 * padRt(d) + 4 * 16 * ZR) * (int)sizeof(float);
        layer15_kernel<<<grid, NTH, smem>>>(
            cw, cb, gw, gb, rw, rb, mix, out,
            li, d, (li == NL - 1) ? 1 : 0);
    }
}

// round 17
// speedup vs baseline: 1.0550x; 1.0550x over previous
#include <cuda_runtime.h>
#include <cuda_bf16.h>

#define TT    65536
#define BB    4
#define W     16
#define NL    18
#define TILEC 512          // ts per CTA (8 warps x 64)
#define NTH   256
#define NW    8
#define ZR    72           // zbuf row stride: >=64 (64 ts/warp row) and mod 32 == 8
#define TFMASK 0xFFFFE000u

// smem float offsets
#define CONVA 0            // conv A frags: ((blk*6+c)*2+hl)*128, 3072 floats
#define RESA  3072         // res A frags: (rc*2+hl)*128, 512 floats
#define MIXO  3584
#define CBO   3600
#define GBO   3616
#define RBO   3632
#define TILEO 3648         // fp32 tile hT[ch][Rt]

typedef unsigned long long u64;
typedef unsigned int u32;

__device__ float g_h0[(size_t)BB * TT * W];   // [b][t][ch]
__device__ float g_h1[(size_t)BB * TT * W];

__device__ __forceinline__ u64 pk(float lo, float hi){ u64 r; asm("mov.b64 %0,{%1,%2};":"=l"(r):"f"(lo),"f"(hi)); return r; }
__device__ __forceinline__ u64 pk2(float x){ u64 r; asm("mov.b64 %0,{%1,%1};":"=l"(r):"f"(x)); return r; }
__device__ __forceinline__ void unpk(u64 v, float& lo, float& hi){ asm("mov.b64 {%0,%1},%2;":"=f"(lo),"=f"(hi):"l"(v)); }
__device__ __forceinline__ u64 fma2(u64 a, u64 b, u64 c){ u64 d; asm("fma.rn.f32x2 %0,%1,%2,%3;":"=l"(d):"l"(a),"l"(b),"l"(c)); return d; }
__device__ __forceinline__ u64 mul2(u64 a, u64 b){ u64 d; asm("mul.rn.f32x2 %0,%1,%2;":"=l"(d):"l"(a),"l"(b)); return d; }
__device__ __forceinline__ u64 add2(u64 a, u64 b){ u64 d; asm("add.rn.f32x2 %0,%1,%2;":"=l"(d):"l"(a),"l"(b)); return d; }
__device__ __forceinline__ float rcpf(float x){ float r; asm("rcp.approx.f32 %0,%1;":"=f"(r):"f"(x)); return r; }

#define ABS2 0x7FFFFFFF7FFFFFFFull
#define ONE2 0x3F8000003F800000ull

__device__ __forceinline__ u64 ssz(u64 f, u64 g){
    u64 df = add2(f & ABS2, ONE2);
    u64 dg = add2(g & ABS2, ONE2);
    u64 dd = mul2(df, dg);
    float dl, dh; unpk(dd, dl, dh);
    u64 rr = pk(rcpf(dl), rcpf(dh));
    return mul2(mul2(f, g), rr);
}

__device__ __forceinline__ void mma8(float* d, const u32* a, u32 b0, u32 b1){
    asm volatile(
        "mma.sync.aligned.m16n8k8.row.col.f32.tf32.tf32.f32 "
        "{%0,%1,%2,%3}, {%4,%5,%6,%7}, {%8,%9}, {%0,%1,%2,%3};"
        : "+f"(d[0]), "+f"(d[1]), "+f"(d[2]), "+f"(d[3])
        : "r"(a[0]), "r"(a[1]), "r"(a[2]), "r"(a[3]), "r"(b0), "r"(b1));
}

__device__ __forceinline__ void tfsplit(float x, u32& hi, u32& lo){
    u32 xb = __float_as_uint(x) & TFMASK;
    hi = xb;
    lo = __float_as_uint(x - __uint_as_float(xb));
}

__global__ void start_kernel(const float* __restrict__ x,
                             const float* __restrict__ sw,
                             float* __restrict__ out) {
    int idx = blockIdx.x * blockDim.x + threadIdx.x;
    if (idx < BB * TT) {
        float xv = x[idx];
        #pragma unroll
        for (int o = 0; o < W; o++) g_h0[(size_t)idx * W + o] = sw[o] * xv;
        out[idx] = 0.f;
    }
}

__host__ __device__ __forceinline__ int padRt(int d) {
    int R = TILEC + 2 * d;
    R += ((8 - (R & 31)) + 32) & 31;   // R % 32 == 8
    return R;
}

// A-fragment swizzle: value (o row 0..15, kk col 0..7) ->
//   lane = (o&7)*4 + (kk&3); reg = (o>>3) + 2*(kk>>2)
__device__ __forceinline__ int fragpos(int o, int kk){
    return ((o & 7) * 4 + (kk & 3)) * 4 + (o >> 3) + 2 * (kk >> 2);
}

__global__ __launch_bounds__(NTH, 2)
void layer16_kernel(const float* __restrict__ cw, const float* __restrict__ cb,
                    const float* __restrict__ gw, const float* __restrict__ gb,
                    const float* __restrict__ rw, const float* __restrict__ rb,
                    const float* __restrict__ mix, float* __restrict__ out,
                    int li, int d, int last)
{
    extern __shared__ float sh[];
    const float* hin  = (li & 1) ? g_h1 : g_h0;
    float*       hout = (li & 1) ? g_h0 : g_h1;
    const int b   = blockIdx.y;
    const int t0  = blockIdx.x * TILEC;
    const int tid = threadIdx.x;
    const int Rt  = padRt(d);
    float* hT = sh + TILEO;
    float* zb = hT + 16 * Rt;

    // ---- conv/gate A prep: tf32 hi/lo split, fragment-swizzled ----
    for (int idx = tid; idx < 1536; idx += NTH) {
        int blk = idx / 768, rem = idx - blk * 768;
        int o = rem / 48, ik = rem - o * 48;
        int i = ik / 3, kt = ik - i * 3;
        float wv = (blk ? gw : cw)[li * 768 + rem];
        u32 hb = __float_as_uint(wv) & TFMASK;
        float hi = __uint_as_float(hb);
        int c = kt * 2 + (i >> 3);
        int base = CONVA + ((blk * 6 + c) * 2) * 128 + fragpos(o, i & 7);
        sh[base]       = hi;
        sh[base + 128] = wv - hi;
    }
    // ---- res A prep ----
    for (int idx = tid; idx < 256; idx += NTH) {
        int o = idx >> 4, i = idx & 15;
        float v = last ? 0.f : rw[li * 256 + idx];
        u32 hb = __float_as_uint(v) & TFMASK;
        float hi = __uint_as_float(hb);
        int base = RESA + ((i >> 3) * 2) * 128 + fragpos(o, i & 7);
        sh[base]       = hi;
        sh[base + 128] = v - hi;
    }
    if (tid < 16) {
        sh[MIXO + tid] = mix[li * 16 + tid];
        sh[CBO  + tid] = cb[li * 16 + tid];
        sh[GBO  + tid] = gb[li * 16 + tid];
        sh[RBO  + tid] = last ? 0.f : rb[li * 16 + tid];
    }

    // ---- fp32 tile load (channel-major, conflict-free) ----
    {
        const int nrows = TILEC + 2 * d;
        for (int r = tid; r < nrows; r += NTH) {
            int gt = t0 - 2 * d + r;
            float4 v0, v1, v2, v3;
            if (gt >= 0) {
                const float4* s = (const float4*)(hin + ((size_t)b * TT + gt) * W);
                v0 = s[0]; v1 = s[1]; v2 = s[2]; v3 = s[3];
            } else {
                v0 = v1 = v2 = v3 = make_float4(0.f, 0.f, 0.f, 0.f);
            }
            hT[ 0 * Rt + r] = v0.x; hT[ 1 * Rt + r] = v0.y;
            hT[ 2 * Rt + r] = v0.z; hT[ 3 * Rt + r] = v0.w;
            hT[ 4 * Rt + r] = v1.x; hT[ 5 * Rt + r] = v1.y;
            hT[ 6 * Rt + r] = v1.z; hT[ 7 * Rt + r] = v1.w;
            hT[ 8 * Rt + r] = v2.x; hT[ 9 * Rt + r] = v2.y;
            hT[10 * Rt + r] = v2.z; hT[11 * Rt + r] = v2.w;
            hT[12 * Rt + r] = v3.x; hT[13 * Rt + r] = v3.y;
            hT[14 * Rt + r] = v3.z; hT[15 * Rt + r] = v3.w;
        }
    }
    __syncthreads();

    // ---- per-warp 64-ts tile ----
    const int lane = tid & 31;
    const int wid  = tid >> 5;
    const int gID  = lane >> 2;
    const int c4   = lane & 3;
    const int tloc = 2 * d + wid * 64;
    const int tw   = t0 + wid * 64;
    float* zw = zb + wid * (16 * ZR);

    // ---- conv+gate GEMM (3xTF32) ----
    float Df[8][4], Dg[8][4];
    {
        float cbl = sh[CBO + gID], cbh = sh[CBO + 8 + gID];
        float gbl = sh[GBO + gID], gbh = sh[GBO + 8 + gID];
        #pragma unroll
        for (int tsb = 0; tsb < 8; tsb++) {
            Df[tsb][0] = cbl; Df[tsb][1] = cbl; Df[tsb][2] = cbh; Df[tsb][3] = cbh;
            Dg[tsb][0] = gbl; Dg[tsb][1] = gbl; Dg[tsb][2] = gbh; Dg[tsb][3] = gbh;
        }
    }

    #pragma unroll
    for (int c = 0; c < 6; c++) {
        const int kt = c >> 1, iB = (c & 1) * 8;
        uint4 AFh = *(const uint4*)&sh[CONVA + ((0*6 + c) * 2 + 0) * 128 + lane * 4];
        uint4 AFl = *(const uint4*)&sh[CONVA + ((0*6 + c) * 2 + 1) * 128 + lane * 4];
        uint4 AGh = *(const uint4*)&sh[CONVA + ((1*6 + c) * 2 + 0) * 128 + lane * 4];
        uint4 AGl = *(const uint4*)&sh[CONVA + ((1*6 + c) * 2 + 1) * 128 + lane * 4];
        const float* t0p = hT + (iB + c4) * Rt;
        const float* t1p = hT + (iB + c4 + 4) * Rt;
        const int tb = tloc - (2 - kt) * d + gID;
        float b0v[8], b1v[8];
        #pragma unroll
        for (int tsb = 0; tsb < 8; tsb++) {
            b0v[tsb] = t0p[tb + tsb * 8];
            b1v[tsb] = t1p[tb + tsb * 8];
        }
        #pragma unroll
        for (int tsb = 0; tsb < 8; tsb++) {
            u32 b0h, b0l, b1h, b1l;
            tfsplit(b0v[tsb], b0h, b0l);
            tfsplit(b1v[tsb], b1h, b1l);
            mma8(Df[tsb], (const u32*)&AFh, b0h, b1h);
            mma8(Dg[tsb], (const u32*)&AGh, b0h, b1h);
            mma8(Df[tsb], (const u32*)&AFh, b0l, b1l);
            mma8(Dg[tsb], (const u32*)&AGh, b0l, b1l);
            mma8(Df[tsb], (const u32*)&AFl, b0h, b1h);
            mma8(Dg[tsb], (const u32*)&AGl, b0h, b1h);
        }
    }

    // ---- gated activation, z -> per-warp zbuf ----
    #pragma unroll
    for (int tsb = 0; tsb < 8; tsb++) {
        u64 z01 = ssz(pk(Df[tsb][0], Df[tsb][1]), pk(Dg[tsb][0], Dg[tsb][1]));
        u64 z23 = ssz(pk(Df[tsb][2], Df[tsb][3]), pk(Dg[tsb][2], Dg[tsb][3]));
        *(u64*)&zw[gID * ZR       + tsb * 8 + 2 * c4] = z01;
        *(u64*)&zw[(gID + 8) * ZR + tsb * 8 + 2 * c4] = z23;
    }
    __syncwarp();

    // ---- mixer: scalar fma2; lane owns ts pair 2*lane ----
    {
        const int t2 = 2 * lane;
        u64 acc = 0ull;
        #pragma unroll
        for (int p = 0; p < 16; p++) {
            u64 zz = *(const u64*)&zw[p * ZR + t2];
            acc = fma2(pk2(sh[MIXO + p]), zz, acc);
        }
        float a, c; unpk(acc, a, c);
        float2* op = (float2*)(out + (size_t)b * TT + tw + t2);
        float2 ov = *op;
        ov.x += a; ov.y += c;
        *op = ov;
    }

    // ---- residual GEMM + hout stores ----
    if (!last) {
        float Dr[8][4];
        {
            float rbl = sh[RBO + gID], rbh = sh[RBO + 8 + gID];
            #pragma unroll
            for (int tsb = 0; tsb < 8; tsb++) {
                int t = tloc + tsb * 8 + 2 * c4;
                float h0, h1, h2, h3;
                { u64 v = *(const u64*)&hT[gID * Rt + t];       unpk(v, h0, h1); }
                { u64 v = *(const u64*)&hT[(gID + 8) * Rt + t]; unpk(v, h2, h3); }
                Dr[tsb][0] = h0 + rbl; Dr[tsb][1] = h1 + rbl;
                Dr[tsb][2] = h2 + rbh; Dr[tsb][3] = h3 + rbh;
            }
        }
        #pragma unroll
        for (int rc = 0; rc < 2; rc++) {
            uint4 ARh = *(const uint4*)&sh[RESA + (rc * 2 + 0) * 128 + lane * 4];
            uint4 ARl = *(const uint4*)&sh[RESA + (rc * 2 + 1) * 128 + lane * 4];
            const float* z0p = zw + (rc * 8 + c4) * ZR + gID;
            const float* z1p = zw + (rc * 8 + c4 + 4) * ZR + gID;
            float b0v[8], b1v[8];
            #pragma unroll
            for (int tsb = 0; tsb < 8; tsb++) {
                b0v[tsb] = z0p[tsb * 8];
                b1v[tsb] = z1p[tsb * 8];
            }
            #pragma unroll
            for (int tsb = 0; tsb < 8; tsb++) {
                u32 b0h, b0l, b1h, b1l;
                tfsplit(b0v[tsb], b0h, b0l);
                tfsplit(b1v[tsb], b1h, b1l);
                mma8(Dr[tsb], (const u32*)&ARh, b0h, b1h);
                mma8(Dr[tsb], (const u32*)&ARh, b0l, b1l);
                mma8(Dr[tsb], (const u32*)&ARl, b0h, b1h);
            }
        }
        #pragma unroll
        for (int tsb = 0; tsb < 8; tsb++) {
            size_t base = ((size_t)b * TT + tw + tsb * 8 + 2 * c4) * W;
            hout[base + gID]         = Dr[tsb][0];
            hout[base + W + gID]     = Dr[tsb][1];
            hout[base + gID + 8]     = Dr[tsb][2];
            hout[base + W + gID + 8] = Dr[tsb][3];
        }
    }
}

extern "C" void kernel_launch(void* const* d_in, const int* in_sizes, int n_in,
                              void* d_out, int out_size) {
    const float* x   = (const float*)d_in[0];
    const float* sw  = (const float*)d_in[1];
    const float* cw  = (const float*)d_in[2];
    const float* cb  = (const float*)d_in[3];
    const float* gw  = (const float*)d_in[4];
    const float* gb  = (const float*)d_in[5];
    const float* rw  = (const float*)d_in[6];
    const float* rb  = (const float*)d_in[7];
    const float* mix = (const float*)d_in[8];
    float* out = (float*)d_out;

    static const int dil[NL] = {1,2,4,8,16,32,64,128,256,
                                1,2,4,8,16,32,64,128,256};

    const int max_smem = (TILEO + 16 * padRt(256) + NW * 16 * ZR) * (int)sizeof(float);
    cudaFuncSetAttribute(layer16_kernel,
                         cudaFuncAttributeMaxDynamicSharedMemorySize, max_smem);

    start_kernel<<<(BB * TT + 255) / 256, 256>>>(x, sw, out);

    dim3 grid(TT / TILEC, BB);
    for (int li = 0; li < NL; li++) {
        int d = dil[li];
        int smem = (TILEO + 16 * padRt(d) + NW * 16 * ZR) * (int)sizeof(float);
        layer16_kernel<<<grid, NTH, smem>>>(
            cw, cb, gw, gb, rw, rb, mix, out,
            li, d, (li == NL - 1) ? 1 : 0);
    }
}